// round 1
// baseline (speedup 1.0000x reference)
#include <cuda_runtime.h>
#include <math.h>

// Problem constants
#define BB   64
#define SS   48
#define HH   512
#define EE   256
#define VV   30000
#define G3   1536   // 3*H
#define KCAT 1024   // 2*H

// ---------------- device scratch (static, no allocations) ----------------
__device__ float g_gi_all[SS * BB * G3];     // encoder gi for all steps (bias included)
__device__ float g_enc_states[BB * SS * HH]; // [B][S][H]
__device__ float g_hA[BB * HH];
__device__ float g_hB[BB * HH];
__device__ float g_gi[BB * G3];
__device__ float g_gh[BB * G3];
__device__ float g_cat[BB * KCAT];
__device__ float g_lse[BB];
__device__ int   g_tok[BB];
__device__ int   g_tokall[SS * BB];

// ---------------- init: h0 = 0, tok = 0, tokall[m = s*B+b] = input[b][s] ----------------
__global__ void init_kernel(const int* __restrict__ input_tensor) {
    int idx = blockIdx.x * blockDim.x + threadIdx.x;
    if (idx < BB * HH) g_hA[idx] = 0.f;
    if (idx < BB) g_tok[idx] = 0;
    if (idx < SS * BB) {
        int s = idx / BB, b = idx % BB;
        g_tokall[idx] = input_tensor[b * SS + s];
    }
}

// ---------------- generic tiled GEMM:  C[M,N] = A[M,K] @ W[N,K]^T + bias ----------------
// Optional row gather: if rowidx != null, A-row m is A[rowidx[m]*K .. ] (embedding lookup).
// BM=BN=64, BK=16, 256 threads, 4x4 micro-tile per thread. K must be a multiple of 16.
__global__ void gemm_nt(const float* __restrict__ A, const int* __restrict__ rowidx,
                        const float* __restrict__ W, const float* __restrict__ bias,
                        float* __restrict__ C, int M, int N, int K) {
    __shared__ float As[16][64];
    __shared__ float Ws[16][64];
    const int bn = blockIdx.x * 64;
    const int bm = blockIdx.y * 64;
    const int tid = threadIdx.x;
    const int tx = tid & 15;   // output col group
    const int ty = tid >> 4;   // output row group
    const int lr = tid >> 2;   // load row 0..63
    const int lk = (tid & 3) * 4;

    float acc[4][4] = {};

    for (int k0 = 0; k0 < K; k0 += 16) {
        int m = bm + lr;
        float4 va = make_float4(0.f, 0.f, 0.f, 0.f);
        if (m < M) {
            const float* Arow = rowidx ? (A + (size_t)rowidx[m] * K) : (A + (size_t)m * K);
            va = *(const float4*)(Arow + k0 + lk);
        }
        As[lk + 0][lr] = va.x; As[lk + 1][lr] = va.y;
        As[lk + 2][lr] = va.z; As[lk + 3][lr] = va.w;

        int n = bn + lr;
        float4 vw = make_float4(0.f, 0.f, 0.f, 0.f);
        if (n < N) vw = *(const float4*)(W + (size_t)n * K + k0 + lk);
        Ws[lk + 0][lr] = vw.x; Ws[lk + 1][lr] = vw.y;
        Ws[lk + 2][lr] = vw.z; Ws[lk + 3][lr] = vw.w;

        __syncthreads();
        #pragma unroll
        for (int kk = 0; kk < 16; kk++) {
            float a[4], w[4];
            *(float4*)a = *(const float4*)&As[kk][ty * 4];
            *(float4*)w = *(const float4*)&Ws[kk][tx * 4];
            #pragma unroll
            for (int i = 0; i < 4; i++)
                #pragma unroll
                for (int j = 0; j < 4; j++)
                    acc[i][j] = fmaf(a[i], w[j], acc[i][j]);
        }
        __syncthreads();
    }

    #pragma unroll
    for (int i = 0; i < 4; i++) {
        int m = bm + ty * 4 + i;
        if (m >= M) continue;
        #pragma unroll
        for (int j = 0; j < 4; j++) {
            int n = bn + tx * 4 + j;
            if (n < N) C[(size_t)m * N + n] = acc[i][j] + bias[n];
        }
    }
}

// ---------------- GRU gates: h' = (1-z)*n + z*h ----------------
__global__ void gru_gates_kernel(const float* __restrict__ gi, const float* __restrict__ gh,
                                 const float* __restrict__ h_old, float* __restrict__ h_new,
                                 int store_enc, int s) {
    int idx = blockIdx.x * blockDim.x + threadIdx.x;
    if (idx >= BB * HH) return;
    int b = idx >> 9;           // /512
    int h = idx & (HH - 1);
    const float* gib = gi + (size_t)b * G3;
    const float* ghb = gh + (size_t)b * G3;
    float r = 1.f / (1.f + expf(-(gib[h] + ghb[h])));
    float z = 1.f / (1.f + expf(-(gib[HH + h] + ghb[HH + h])));
    float n = tanhf(gib[2 * HH + h] + r * ghb[2 * HH + h]);
    float hv = (1.f - z) * n + z * h_old[idx];
    h_new[idx] = hv;
    if (store_enc) g_enc_states[((size_t)b * SS + s) * HH + h] = hv;
}

// ---------------- attention + build cat = [h_new, context] ----------------
// one block per batch row, 256 threads (8 warps x 6 scores each)
__global__ void attn_kernel(const float* __restrict__ hnew) {
    int b = blockIdx.x;
    int tid = threadIdx.x;
    int lane = tid & 31, w = tid >> 5;
    __shared__ float sc[SS];
    const float* es = g_enc_states + (size_t)b * SS * HH;
    const float* hb = hnew + b * HH;

    #pragma unroll
    for (int i = 0; i < 6; i++) {
        int s = w * 6 + i;
        const float* row = es + s * HH;
        float sum = 0.f;
        for (int h = lane; h < HH; h += 32) sum = fmaf(row[h], hb[h], sum);
        #pragma unroll
        for (int o = 16; o > 0; o >>= 1) sum += __shfl_down_sync(0xffffffffu, sum, o);
        if (lane == 0) sc[s] = sum;
    }
    __syncthreads();

    if (w == 0) {
        float v0 = (lane < SS) ? sc[lane] : -INFINITY;
        float v1 = (lane + 32 < SS) ? sc[lane + 32] : -INFINITY;
        float m = fmaxf(v0, v1);
        #pragma unroll
        for (int o = 16; o > 0; o >>= 1) m = fmaxf(m, __shfl_xor_sync(0xffffffffu, m, o));
        float e0 = (lane < SS) ? expf(v0 - m) : 0.f;
        float e1 = (lane + 32 < SS) ? expf(v1 - m) : 0.f;
        float s = e0 + e1;
        #pragma unroll
        for (int o = 16; o > 0; o >>= 1) s += __shfl_xor_sync(0xffffffffu, s, o);
        if (lane < SS) sc[lane] = e0 / s;
        if (lane + 32 < SS) sc[lane + 32] = e1 / s;
    }
    __syncthreads();

    for (int h = tid; h < HH; h += 256) {
        float c = 0.f;
        #pragma unroll 8
        for (int s = 0; s < SS; s++) c = fmaf(sc[s], es[s * HH + h], c);
        g_cat[b * KCAT + HH + h] = c;
        g_cat[b * KCAT + h] = hb[h];
    }
}

// ---------------- argmax + logsumexp per batch row over V=30000 ----------------
__global__ void argmax_lse_kernel(const float* __restrict__ logits,
                                  float* __restrict__ pred, int t) {
    int b = blockIdx.x;
    int tid = threadIdx.x;
    const float* row = logits + (size_t)b * VV;

    float bm = -INFINITY; int bi = 0;
    for (int v = tid; v < VV; v += 256) {
        float x = row[v];
        if (x > bm) { bm = x; bi = v; }   // within-thread v strictly increases
    }
    __shared__ float smv[256];
    __shared__ int   smi[256];
    smv[tid] = bm; smi[tid] = bi;
    __syncthreads();
    for (int o = 128; o > 0; o >>= 1) {
        if (tid < o) {
            float ov = smv[tid + o]; int oi = smi[tid + o];
            if (ov > smv[tid] || (ov == smv[tid] && oi < smi[tid])) {
                smv[tid] = ov; smi[tid] = oi;
            }
        }
        __syncthreads();
    }
    float gmax = smv[0];
    int gidx = smi[0];

    float s = 0.f;
    for (int v = tid; v < VV; v += 256) s += expf(row[v] - gmax);
    __shared__ float ssum[256];
    ssum[tid] = s;
    __syncthreads();
    for (int o = 128; o > 0; o >>= 1) {
        if (tid < o) ssum[tid] += ssum[tid + o];
        __syncthreads();
    }
    if (tid == 0) {
        g_lse[b] = gmax + logf(ssum[0]);
        g_tok[b] = gidx;
        pred[t * BB + b] = (float)gidx;
    }
}

// ---------------- logits -> log_probs in place ----------------
__global__ void sub_lse_kernel(float* __restrict__ slab) {
    int idx = blockIdx.x * blockDim.x + threadIdx.x;
    if (idx < BB * VV) {
        int b = idx / VV;
        slab[idx] -= g_lse[b];
    }
}

// ---------------- host driver (graph-capturable: kernel launches only) ----------------
extern "C" void kernel_launch(void* const* d_in, const int* in_sizes, int n_in,
                              void* d_out, int out_size) {
    const int*   input_tensor = (const int*)d_in[0];
    const float* enc_embed    = (const float*)d_in[1];
    const float* enc_wih      = (const float*)d_in[2];
    const float* enc_whh      = (const float*)d_in[3];
    const float* enc_bih      = (const float*)d_in[4];
    const float* enc_bhh      = (const float*)d_in[5];
    const float* dec_embed    = (const float*)d_in[6];
    const float* dec_wih      = (const float*)d_in[7];
    const float* dec_whh      = (const float*)d_in[8];
    const float* dec_bih      = (const float*)d_in[9];
    const float* dec_bhh      = (const float*)d_in[10];
    const float* proj_w       = (const float*)d_in[11];
    const float* proj_b       = (const float*)d_in[12];

    float* out   = (float*)d_out;
    float* pred  = out;            // [S,B] as float
    float* dists = out + SS * BB;  // [S,B,V]

    float *p_gi_all, *p_hA, *p_hB, *p_gi, *p_gh, *p_cat;
    int *p_tokall, *p_tok;
    cudaGetSymbolAddress((void**)&p_gi_all, g_gi_all);
    cudaGetSymbolAddress((void**)&p_hA, g_hA);
    cudaGetSymbolAddress((void**)&p_hB, g_hB);
    cudaGetSymbolAddress((void**)&p_gi, g_gi);
    cudaGetSymbolAddress((void**)&p_gh, g_gh);
    cudaGetSymbolAddress((void**)&p_cat, g_cat);
    cudaGetSymbolAddress((void**)&p_tokall, g_tokall);
    cudaGetSymbolAddress((void**)&p_tok, g_tok);

    init_kernel<<<(BB * HH + 255) / 256, 256>>>(input_tensor);

    // Encoder: all-step input-side GEMM in one shot (gather embeddings on the fly)
    gemm_nt<<<dim3(G3 / 64, (SS * BB) / 64), 256>>>(
        enc_embed, p_tokall, enc_wih, enc_bih, p_gi_all, SS * BB, G3, EE);

    // Encoder recurrence
    for (int s = 0; s < SS; s++) {
        float* hin  = (s & 1) ? p_hB : p_hA;
        float* hout = (s & 1) ? p_hA : p_hB;
        gemm_nt<<<dim3(G3 / 64, 1), 256>>>(hin, nullptr, enc_whh, enc_bhh, p_gh, BB, G3, HH);
        gru_gates_kernel<<<(BB * HH) / 256, 256>>>(
            p_gi_all + (size_t)s * BB * G3, p_gh, hin, hout, 1, s);
    }
    // after step 47 (odd), enc_last lives in g_hA

    // Decoder (autoregressive)
    for (int t = 0; t < SS; t++) {
        float* hin  = (t & 1) ? p_hB : p_hA;
        float* hout = (t & 1) ? p_hA : p_hB;
        gemm_nt<<<dim3(G3 / 64, 1), 256>>>(dec_embed, p_tok, dec_wih, dec_bih, p_gi, BB, G3, EE);
        gemm_nt<<<dim3(G3 / 64, 1), 256>>>(hin, nullptr, dec_whh, dec_bhh, p_gh, BB, G3, HH);
        gru_gates_kernel<<<(BB * HH) / 256, 256>>>(p_gi, p_gh, hin, hout, 0, 0);
        attn_kernel<<<BB, 256>>>(hout);

        float* slab = dists + (size_t)t * BB * VV;
        gemm_nt<<<dim3((VV + 63) / 64, 1), 256>>>(p_cat, nullptr, proj_w, proj_b, slab, BB, VV, KCAT);
        argmax_lse_kernel<<<BB, 256>>>(slab, pred, t);
        sub_lse_kernel<<<(BB * VV + 255) / 256, 256>>>(slab);
    }
}

// round 3
// speedup vs baseline: 1.3870x; 1.3870x over previous
#include <cuda_runtime.h>
#include <math.h>
#include <stdint.h>

// Problem constants
#define BB   64
#define SS   48
#define HH   512
#define EE   256
#define VV   30000
#define G3   1536   // 3*H
#define KCAT 1024   // 2*H

// ---------------- device scratch (static, no allocations) ----------------
__device__ float g_gi_all[SS * BB * G3];     // encoder gi for all steps (bias included)
__device__ float g_enc_states[BB * SS * HH]; // [B][S][H]
__device__ float g_hA[BB * HH];
__device__ float g_hB[BB * HH];
__device__ float g_gi[BB * G3];
__device__ float g_gh[BB * G3];
__device__ float g_cat[BB * KCAT];
__device__ int   g_tok[BB];
__device__ int   g_tokall[SS * BB];

// ---------------- init ----------------
__global__ void init_kernel(const int* __restrict__ input_tensor) {
    int idx = blockIdx.x * blockDim.x + threadIdx.x;
    if (idx < BB * HH) g_hA[idx] = 0.f;
    if (idx < BB) g_tok[idx] = 0;
    if (idx < SS * BB) {
        int s = idx / BB, b = idx % BB;
        g_tokall[idx] = input_tensor[b * SS + s];
    }
}

// ---------------- tf32 helpers ----------------
__device__ __forceinline__ uint32_t f2tf32(float x) {
    uint32_t r;
    asm("cvt.rna.tf32.f32 %0, %1;" : "=r"(r) : "f"(x));
    return r;
}
__device__ __forceinline__ void split_tf32(float x, float& hi, float& lo) {
    hi = __uint_as_float(f2tf32(x));
    lo = __uint_as_float(f2tf32(x - hi));
}
__device__ __forceinline__ void mma_tf32(float* c, const uint32_t* a, const uint32_t* b) {
    asm volatile(
        "mma.sync.aligned.m16n8k8.row.col.f32.tf32.tf32.f32 "
        "{%0,%1,%2,%3},{%4,%5,%6,%7},{%8,%9},{%0,%1,%2,%3};"
        : "+f"(c[0]), "+f"(c[1]), "+f"(c[2]), "+f"(c[3])
        : "r"(a[0]), "r"(a[1]), "r"(a[2]), "r"(a[3]), "r"(b[0]), "r"(b[1]));
}

// ================= 3xTF32 GEMM:  C[M,N] = A[M,K] @ W[N,K]^T + bias =================
// BM=64 (grid.y), BN=64 (grid.x), BK=16, 128 threads (4 warps, each 32x32 C tile).
// M must be a multiple of 64 (true for all call sites). N guarded. K multiple of 16.
// Optional rowidx gathers A rows (embedding lookup).
// Smem: per buffer, hi/lo tiles of A and W, rows padded to 20 floats (conflict-free
// fragment LDS: bank = (20*g + t) & 31 covers all 32 banks).
#define SP 20

__device__ __forceinline__ void gemm3tf32_dev(
    const float* __restrict__ A, const int* __restrict__ rowidx,
    const float* __restrict__ W, const float* __restrict__ bias,
    float* __restrict__ C, int N, int K)
{
    __shared__ __align__(16) float smem[2][4][64 * SP];  // [buf][a_hi,a_lo,w_hi,w_lo]

    const int tid  = threadIdx.x;
    const int lane = tid & 31;
    const int wid  = tid >> 5;
    const int wm   = wid >> 1;         // 0..1
    const int wn   = wid & 1;          // 0..1
    const int g    = lane >> 2;        // 0..7
    const int tg   = lane & 3;         // 0..3

    const int bn = blockIdx.x * 64;
    const int bm = blockIdx.y * 64;

    // loader mapping: each thread loads row lrow, 8 consecutive cols (2 float4)
    const int lrow = tid >> 1;         // 0..63
    const int lcb  = (tid & 1) * 8;    // 0 or 8

    const float* Arow = rowidx ? (A + (size_t)rowidx[bm + lrow] * K)
                               : (A + (size_t)(bm + lrow) * K);
    const int nW = bn + lrow;
    const bool wok = (nW < N);
    const float* Wrow = W + (size_t)(wok ? nW : 0) * K;

    float4 va0, va1, vw0, vw1;

    float acc[2][4][4];
    #pragma unroll
    for (int mi = 0; mi < 2; mi++)
        #pragma unroll
        for (int ni = 0; ni < 4; ni++)
            #pragma unroll
            for (int q = 0; q < 4; q++) acc[mi][ni][q] = 0.f;

    const int ntiles = K >> 4;

    // ---- load regs for tile 0 ----
    va0 = *(const float4*)(Arow + lcb);
    va1 = *(const float4*)(Arow + lcb + 4);
    if (wok) { vw0 = *(const float4*)(Wrow + lcb); vw1 = *(const float4*)(Wrow + lcb + 4); }
    else     { vw0 = make_float4(0,0,0,0); vw1 = vw0; }

    // ---- store tile 0 into buffer 0 ----
    {
        float* sah = smem[0][0]; float* sal = smem[0][1];
        float* swh = smem[0][2]; float* swl = smem[0][3];
        float4 h4, l4;
        split_tf32(va0.x, h4.x, l4.x); split_tf32(va0.y, h4.y, l4.y);
        split_tf32(va0.z, h4.z, l4.z); split_tf32(va0.w, h4.w, l4.w);
        *(float4*)&sah[lrow * SP + lcb] = h4; *(float4*)&sal[lrow * SP + lcb] = l4;
        split_tf32(va1.x, h4.x, l4.x); split_tf32(va1.y, h4.y, l4.y);
        split_tf32(va1.z, h4.z, l4.z); split_tf32(va1.w, h4.w, l4.w);
        *(float4*)&sah[lrow * SP + lcb + 4] = h4; *(float4*)&sal[lrow * SP + lcb + 4] = l4;
        split_tf32(vw0.x, h4.x, l4.x); split_tf32(vw0.y, h4.y, l4.y);
        split_tf32(vw0.z, h4.z, l4.z); split_tf32(vw0.w, h4.w, l4.w);
        *(float4*)&swh[lrow * SP + lcb] = h4; *(float4*)&swl[lrow * SP + lcb] = l4;
        split_tf32(vw1.x, h4.x, l4.x); split_tf32(vw1.y, h4.y, l4.y);
        split_tf32(vw1.z, h4.z, l4.z); split_tf32(vw1.w, h4.w, l4.w);
        *(float4*)&swh[lrow * SP + lcb + 4] = h4; *(float4*)&swl[lrow * SP + lcb + 4] = l4;
    }
    __syncthreads();

    for (int t = 0; t < ntiles; t++) {
        // prefetch next tile into registers
        if (t + 1 < ntiles) {
            const int k0 = (t + 1) << 4;
            va0 = *(const float4*)(Arow + k0 + lcb);
            va1 = *(const float4*)(Arow + k0 + lcb + 4);
            if (wok) { vw0 = *(const float4*)(Wrow + k0 + lcb); vw1 = *(const float4*)(Wrow + k0 + lcb + 4); }
            else     { vw0 = make_float4(0,0,0,0); vw1 = vw0; }
        }

        // compute on current buffer
        {
            const int buf = t & 1;
            const float* sah = smem[buf][0]; const float* sal = smem[buf][1];
            const float* swh = smem[buf][2]; const float* swl = smem[buf][3];
            #pragma unroll
            for (int ks = 0; ks < 2; ks++) {
                const int kk = ks * 8;
                uint32_t ah[2][4], al[2][4];
                #pragma unroll
                for (int mi = 0; mi < 2; mi++) {
                    int r0 = (wm * 32 + mi * 16 + g) * SP + kk + tg;
                    ah[mi][0] = __float_as_uint(sah[r0]);
                    ah[mi][1] = __float_as_uint(sah[r0 + 8 * SP]);
                    ah[mi][2] = __float_as_uint(sah[r0 + 4]);
                    ah[mi][3] = __float_as_uint(sah[r0 + 8 * SP + 4]);
                    al[mi][0] = __float_as_uint(sal[r0]);
                    al[mi][1] = __float_as_uint(sal[r0 + 8 * SP]);
                    al[mi][2] = __float_as_uint(sal[r0 + 4]);
                    al[mi][3] = __float_as_uint(sal[r0 + 8 * SP + 4]);
                }
                uint32_t bh[4][2], bl[4][2];
                #pragma unroll
                for (int ni = 0; ni < 4; ni++) {
                    int rn = (wn * 32 + ni * 8 + g) * SP + kk + tg;
                    bh[ni][0] = __float_as_uint(swh[rn]);
                    bh[ni][1] = __float_as_uint(swh[rn + 4]);
                    bl[ni][0] = __float_as_uint(swl[rn]);
                    bl[ni][1] = __float_as_uint(swl[rn + 4]);
                }
                #pragma unroll
                for (int mi = 0; mi < 2; mi++)
                    #pragma unroll
                    for (int ni = 0; ni < 4; ni++) {
                        mma_tf32(acc[mi][ni], ah[mi], bh[ni]);
                        mma_tf32(acc[mi][ni], ah[mi], bl[ni]);
                        mma_tf32(acc[mi][ni], al[mi], bh[ni]);
                    }
            }
        }

        // store prefetched tile into other buffer
        if (t + 1 < ntiles) {
            const int buf = (t + 1) & 1;
            float* sah = smem[buf][0]; float* sal = smem[buf][1];
            float* swh = smem[buf][2]; float* swl = smem[buf][3];
            float4 h4, l4;
            split_tf32(va0.x, h4.x, l4.x); split_tf32(va0.y, h4.y, l4.y);
            split_tf32(va0.z, h4.z, l4.z); split_tf32(va0.w, h4.w, l4.w);
            *(float4*)&sah[lrow * SP + lcb] = h4; *(float4*)&sal[lrow * SP + lcb] = l4;
            split_tf32(va1.x, h4.x, l4.x); split_tf32(va1.y, h4.y, l4.y);
            split_tf32(va1.z, h4.z, l4.z); split_tf32(va1.w, h4.w, l4.w);
            *(float4*)&sah[lrow * SP + lcb + 4] = h4; *(float4*)&sal[lrow * SP + lcb + 4] = l4;
            split_tf32(vw0.x, h4.x, l4.x); split_tf32(vw0.y, h4.y, l4.y);
            split_tf32(vw0.z, h4.z, l4.z); split_tf32(vw0.w, h4.w, l4.w);
            *(float4*)&swh[lrow * SP + lcb] = h4; *(float4*)&swl[lrow * SP + lcb] = l4;
            split_tf32(vw1.x, h4.x, l4.x); split_tf32(vw1.y, h4.y, l4.y);
            split_tf32(vw1.z, h4.z, l4.z); split_tf32(vw1.w, h4.w, l4.w);
            *(float4*)&swh[lrow * SP + lcb + 4] = h4; *(float4*)&swl[lrow * SP + lcb + 4] = l4;
        }
        __syncthreads();
    }

    // ---- epilogue: bias + guarded store (cols even, N even -> float2 safe) ----
    #pragma unroll
    for (int mi = 0; mi < 2; mi++) {
        #pragma unroll
        for (int ni = 0; ni < 4; ni++) {
            int col = bn + wn * 32 + ni * 8 + 2 * tg;
            if (col >= N) continue;
            float2 bb = *(const float2*)&bias[col];
            int row0 = bm + wm * 32 + mi * 16 + g;
            float2 v0 = make_float2(acc[mi][ni][0] + bb.x, acc[mi][ni][1] + bb.y);
            float2 v1 = make_float2(acc[mi][ni][2] + bb.x, acc[mi][ni][3] + bb.y);
            *(float2*)&C[(size_t)row0 * N + col] = v0;
            *(float2*)&C[(size_t)(row0 + 8) * N + col] = v1;
        }
    }
}

__global__ void gemm3tf32_k(const float* __restrict__ A, const int* __restrict__ rowidx,
                            const float* __restrict__ W, const float* __restrict__ bias,
                            float* __restrict__ C, int N, int K) {
    gemm3tf32_dev(A, rowidx, W, bias, C, N, K);
}

// fused decoder gi (z=0) + gh (z=1) in one launch
__global__ void dec_gigh_k(const float* __restrict__ dec_embed, const int* __restrict__ tok,
                           const float* __restrict__ wih, const float* __restrict__ bih,
                           float* __restrict__ gi,
                           const float* __restrict__ hin, const float* __restrict__ whh,
                           const float* __restrict__ bhh, float* __restrict__ gh) {
    if (blockIdx.z == 0) gemm3tf32_dev(dec_embed, tok, wih, bih, gi, G3, EE);
    else                 gemm3tf32_dev(hin, nullptr, whh, bhh, gh, G3, HH);
}

// ---------------- encoder GRU gates (also stores enc_states) ----------------
__global__ void gru_gates_kernel(const float* __restrict__ gi, const float* __restrict__ gh,
                                 const float* __restrict__ h_old, float* __restrict__ h_new,
                                 int s) {
    int idx = blockIdx.x * blockDim.x + threadIdx.x;
    if (idx >= BB * HH) return;
    int b = idx >> 9;
    int h = idx & (HH - 1);
    const float* gib = gi + (size_t)b * G3;
    const float* ghb = gh + (size_t)b * G3;
    float r = 1.f / (1.f + expf(-(gib[h] + ghb[h])));
    float z = 1.f / (1.f + expf(-(gib[HH + h] + ghb[HH + h])));
    float n = tanhf(gib[2 * HH + h] + r * ghb[2 * HH + h]);
    float hv = (1.f - z) * n + z * h_old[idx];
    h_new[idx] = hv;
    g_enc_states[((size_t)b * SS + s) * HH + h] = hv;
}

// ---------------- fused decoder gates + attention + cat build ----------------
// one block per batch row, 256 threads
__global__ void gates_attn_kernel(const float* __restrict__ gi, const float* __restrict__ gh,
                                  const float* __restrict__ hin, float* __restrict__ hout) {
    int b = blockIdx.x;
    int tid = threadIdx.x;
    int lane = tid & 31, w = tid >> 5;
    __shared__ float hsm[HH];
    __shared__ float sc[SS];

    const float* gib = gi + (size_t)b * G3;
    const float* ghb = gh + (size_t)b * G3;
    const float* hob = hin + (size_t)b * HH;

    for (int h = tid; h < HH; h += 256) {
        float r = 1.f / (1.f + expf(-(gib[h] + ghb[h])));
        float z = 1.f / (1.f + expf(-(gib[HH + h] + ghb[HH + h])));
        float n = tanhf(gib[2 * HH + h] + r * ghb[2 * HH + h]);
        float hv = (1.f - z) * n + z * hob[h];
        hout[(size_t)b * HH + h] = hv;
        hsm[h] = hv;
        g_cat[b * KCAT + h] = hv;
    }
    __syncthreads();

    const float* es = g_enc_states + (size_t)b * SS * HH;

    #pragma unroll
    for (int i = 0; i < 6; i++) {
        int s = w * 6 + i;
        const float* row = es + s * HH;
        float sum = 0.f;
        for (int h = lane; h < HH; h += 32) sum = fmaf(row[h], hsm[h], sum);
        #pragma unroll
        for (int o = 16; o > 0; o >>= 1) sum += __shfl_down_sync(0xffffffffu, sum, o);
        if (lane == 0) sc[s] = sum;
    }
    __syncthreads();

    if (w == 0) {
        float v0 = (lane < SS) ? sc[lane] : -INFINITY;
        float v1 = (lane + 32 < SS) ? sc[lane + 32] : -INFINITY;
        float m = fmaxf(v0, v1);
        #pragma unroll
        for (int o = 16; o > 0; o >>= 1) m = fmaxf(m, __shfl_xor_sync(0xffffffffu, m, o));
        float e0 = (lane < SS) ? expf(v0 - m) : 0.f;
        float e1 = (lane + 32 < SS) ? expf(v1 - m) : 0.f;
        float s = e0 + e1;
        #pragma unroll
        for (int o = 16; o > 0; o >>= 1) s += __shfl_xor_sync(0xffffffffu, s, o);
        if (lane < SS) sc[lane] = e0 / s;
        if (lane + 32 < SS) sc[lane + 32] = e1 / s;
    }
    __syncthreads();

    for (int h = tid; h < HH; h += 256) {
        float c = 0.f;
        #pragma unroll 8
        for (int s = 0; s < SS; s++) c = fmaf(sc[s], es[s * HH + h], c);
        g_cat[b * KCAT + HH + h] = c;
    }
}

// ---------------- fused argmax + logsumexp + in-place log_softmax ----------------
__global__ void argmax_lse_sub_kernel(float* __restrict__ slab,
                                      float* __restrict__ pred, int t) {
    int b = blockIdx.x;
    int tid = threadIdx.x;
    float* row = slab + (size_t)b * VV;

    // pass 1: max + argmax
    float bm = -INFINITY; int bi = 0;
    for (int v = tid; v < VV; v += 256) {
        float x = row[v];
        if (x > bm) { bm = x; bi = v; }
    }
    __shared__ float smv[256];
    __shared__ int   smi[256];
    smv[tid] = bm; smi[tid] = bi;
    __syncthreads();
    for (int o = 128; o > 0; o >>= 1) {
        if (tid < o) {
            float ov = smv[tid + o]; int oi = smi[tid + o];
            if (ov > smv[tid] || (ov == smv[tid] && oi < smi[tid])) {
                smv[tid] = ov; smi[tid] = oi;
            }
        }
        __syncthreads();
    }
    float gmax = smv[0];
    int gidx = smi[0];

    // pass 2: sum exp
    float s = 0.f;
    for (int v = tid; v < VV; v += 256) s += expf(row[v] - gmax);
    __shared__ float ssum[256];
    ssum[tid] = s;
    __syncthreads();
    for (int o = 128; o > 0; o >>= 1) {
        if (tid < o) ssum[tid] += ssum[tid + o];
        __syncthreads();
    }
    float lse = gmax + logf(ssum[0]);

    // pass 3: log_probs in place
    for (int v = tid; v < VV; v += 256) row[v] -= lse;

    if (tid == 0) {
        g_tok[b] = gidx;
        pred[t * BB + b] = (float)gidx;
    }
}

// ---------------- host driver ----------------
extern "C" void kernel_launch(void* const* d_in, const int* in_sizes, int n_in,
                              void* d_out, int out_size) {
    const int*   input_tensor = (const int*)d_in[0];
    const float* enc_embed    = (const float*)d_in[1];
    const float* enc_wih      = (const float*)d_in[2];
    const float* enc_whh      = (const float*)d_in[3];
    const float* enc_bih      = (const float*)d_in[4];
    const float* enc_bhh      = (const float*)d_in[5];
    const float* dec_embed    = (const float*)d_in[6];
    const float* dec_wih      = (const float*)d_in[7];
    const float* dec_whh      = (const float*)d_in[8];
    const float* dec_bih      = (const float*)d_in[9];
    const float* dec_bhh      = (const float*)d_in[10];
    const float* proj_w       = (const float*)d_in[11];
    const float* proj_b       = (const float*)d_in[12];

    float* out   = (float*)d_out;
    float* pred  = out;            // [S,B] as float
    float* dists = out + SS * BB;  // [S,B,V]

    float *p_gi_all, *p_hA, *p_hB, *p_gi, *p_gh, *p_cat;
    int *p_tokall, *p_tok;
    cudaGetSymbolAddress((void**)&p_gi_all, g_gi_all);
    cudaGetSymbolAddress((void**)&p_hA, g_hA);
    cudaGetSymbolAddress((void**)&p_hB, g_hB);
    cudaGetSymbolAddress((void**)&p_gi, g_gi);
    cudaGetSymbolAddress((void**)&p_gh, g_gh);
    cudaGetSymbolAddress((void**)&p_cat, g_cat);
    cudaGetSymbolAddress((void**)&p_tokall, g_tokall);
    cudaGetSymbolAddress((void**)&p_tok, g_tok);

    init_kernel<<<(BB * HH + 255) / 256, 256>>>(input_tensor);

    // Encoder: all-step input-side GEMM (gather embeddings), M = S*B = 3072
    gemm3tf32_k<<<dim3(G3 / 64, (SS * BB) / 64), 128>>>(
        enc_embed, p_tokall, enc_wih, enc_bih, p_gi_all, G3, EE);

    // Encoder recurrence
    for (int s = 0; s < SS; s++) {
        float* hin  = (s & 1) ? p_hB : p_hA;
        float* hout = (s & 1) ? p_hA : p_hB;
        gemm3tf32_k<<<dim3(G3 / 64, 1), 128>>>(hin, nullptr, enc_whh, enc_bhh, p_gh, G3, HH);
        gru_gates_kernel<<<(BB * HH) / 256, 256>>>(
            p_gi_all + (size_t)s * BB * G3, p_gh, hin, hout, s);
    }
    // after step 47 (odd), enc_last lives in g_hA

    // Decoder (autoregressive)
    for (int t = 0; t < SS; t++) {
        float* hin  = (t & 1) ? p_hB : p_hA;
        float* hout = (t & 1) ? p_hA : p_hB;

        dec_gigh_k<<<dim3(G3 / 64, 1, 2), 128>>>(
            dec_embed, p_tok, dec_wih, dec_bih, p_gi,
            hin, dec_whh, dec_bhh, p_gh);

        gates_attn_kernel<<<BB, 256>>>(p_gi, p_gh, hin, hout);

        float* slab = dists + (size_t)t * BB * VV;
        gemm3tf32_k<<<dim3((VV + 63) / 64, 1), 128>>>(
            p_cat, nullptr, proj_w, proj_b, slab, VV, KCAT);

        argmax_lse_sub_kernel<<<BB, 256>>>(slab, pred, t);
    }
}